// round 2
// baseline (speedup 1.0000x reference)
#include <cuda_runtime.h>
#include <cuda_bf16.h>

#define G      500
#define DN     128
#define DE     64
#define DG     128
#define DO     128
#define SLICES 8

// Device scratch (no allocation allowed)
__device__ int   g_noff[G + 1];
__device__ int   g_eoff[G + 1];
__device__ float g_nagg[G * DN];   // raw sums (scaled in out_kernel)
__device__ float g_eagg[G * DE];

// ---------------------------------------------------------------------------
// Kernel 0: parallel prefix scans (block 0 = nodes, block 1 = edges) + all 64
// blocks zero the accumulator arrays for the atomic aggregation.
// ---------------------------------------------------------------------------
__global__ __launch_bounds__(512) void scan_zero_kernel(const int* __restrict__ nn,
                                                        const int* __restrict__ ne) {
    const int b = blockIdx.x, t = threadIdx.x;

    // Zero accumulators (distributed across all blocks)
    for (int i = b * 512 + t; i < G * DN; i += gridDim.x * 512) g_nagg[i] = 0.f;
    for (int i = b * 512 + t; i < G * DE; i += gridDim.x * 512) g_eagg[i] = 0.f;

    if (b < 2) {
        const int* len = (b == 0) ? nn : ne;
        int*       off = (b == 0) ? g_noff : g_eoff;
        const int lane = t & 31, w = t >> 5;

        int v = (t < G) ? len[t] : 0;
        #pragma unroll
        for (int d = 1; d < 32; d <<= 1) {
            int u = __shfl_up_sync(0xffffffffu, v, d);
            if (lane >= d) v += u;
        }
        __shared__ int wt[16];
        if (lane == 31) wt[w] = v;
        __syncthreads();
        if (w == 0) {
            int x = (lane < 16) ? wt[lane] : 0;
            #pragma unroll
            for (int d = 1; d < 16; d <<= 1) {
                int u = __shfl_up_sync(0xffffffffu, x, d);
                if (lane >= d) x += u;
            }
            if (lane < 16) wt[lane] = x;
        }
        __syncthreads();
        const int base = (w > 0) ? wt[w - 1] : 0;
        if (t < G) off[t + 1] = v + base;
        if (t == 0) off[0] = 0;
    }
}

// ---------------------------------------------------------------------------
// Kernel 1: sliced segment-sum. 8 blocks per graph per stream. Blocks
// [0, 4000) = node slices, [4000, 8000) = edge slices. 256 threads, float4
// coalesced loads, smem tree reduce, atomicAdd (REDG) partials into globals.
// ---------------------------------------------------------------------------
__global__ __launch_bounds__(256) void agg_kernel(const float4* __restrict__ nf4,
                                                  const float4* __restrict__ ef4) {
    __shared__ float4 red[256];
    const int b   = blockIdx.x;
    const int tid = threadIdx.x;

    if (b < G * SLICES) {
        // ---- node slice: 32 float4 cols x 8 row-groups ----
        const int g    = b >> 3;
        const int s    = b & 7;
        const int lane = tid & 31;
        const int rg   = tid >> 5;
        const int off0 = g_noff[g];
        const int n    = g_noff[g + 1] - off0;
        const int r0   = (int)((long long)n * s / SLICES);
        const int r1   = (int)((long long)n * (s + 1) / SLICES);
        const float4* base = nf4 + (size_t)off0 * 32 + lane;

        float4 acc = make_float4(0.f, 0.f, 0.f, 0.f);
        #pragma unroll 4
        for (int r = r0 + rg; r < r1; r += 8) {
            float4 v = __ldg(&base[(size_t)r * 32]);
            acc.x += v.x; acc.y += v.y; acc.z += v.z; acc.w += v.w;
        }
        red[rg * 32 + lane] = acc;
        __syncthreads();
        #pragma unroll
        for (int st = 4; st >= 1; st >>= 1) {
            if (rg < st) {
                float4 o = red[(rg + st) * 32 + lane];
                float4 m = red[rg * 32 + lane];
                m.x += o.x; m.y += o.y; m.z += o.z; m.w += o.w;
                red[rg * 32 + lane] = m;
            }
            __syncthreads();
        }
        if (rg == 0) {
            float4 m = red[lane];
            float* dst = g_nagg + g * DN + lane * 4;
            atomicAdd(dst + 0, m.x);
            atomicAdd(dst + 1, m.y);
            atomicAdd(dst + 2, m.z);
            atomicAdd(dst + 3, m.w);
        }
    } else {
        // ---- edge slice: 16 float4 cols x 16 row-groups ----
        const int bb   = b - G * SLICES;
        const int g    = bb >> 3;
        const int s    = bb & 7;
        const int lane = tid & 15;
        const int rg   = tid >> 4;
        const int off0 = g_eoff[g];
        const int n    = g_eoff[g + 1] - off0;
        const int r0   = (int)((long long)n * s / SLICES);
        const int r1   = (int)((long long)n * (s + 1) / SLICES);
        const float4* base = ef4 + (size_t)off0 * 16 + lane;

        float4 acc = make_float4(0.f, 0.f, 0.f, 0.f);
        #pragma unroll 4
        for (int r = r0 + rg; r < r1; r += 16) {
            float4 v = __ldg(&base[(size_t)r * 16]);
            acc.x += v.x; acc.y += v.y; acc.z += v.z; acc.w += v.w;
        }
        red[rg * 16 + lane] = acc;
        __syncthreads();
        #pragma unroll
        for (int st = 8; st >= 1; st >>= 1) {
            if (rg < st) {
                float4 o = red[(rg + st) * 16 + lane];
                float4 m = red[rg * 16 + lane];
                m.x += o.x; m.y += o.y; m.z += o.z; m.w += o.w;
                red[rg * 16 + lane] = m;
            }
            __syncthreads();
        }
        if (rg == 0) {
            float4 m = red[lane];
            float* dst = g_eagg + g * DE + lane * 4;
            atomicAdd(dst + 0, m.x);
            atomicAdd(dst + 1, m.y);
            atomicAdd(dst + 2, m.z);
            atomicAdd(dst + 3, m.w);
        }
    }
}

// ---------------------------------------------------------------------------
// Kernel 2: out[g][o] = <nsum[g],Wn[o]>/n + <esum[g],We[o]>/e
//                       + <gf[g],Wg[o]> + b[o]
// One warp per (g,o) task; coalesced W reads; butterfly reduce.
// ---------------------------------------------------------------------------
__global__ __launch_bounds__(256) void out_kernel(const float* __restrict__ gf,
                                                  const float* __restrict__ Wn,
                                                  const float* __restrict__ We,
                                                  const float* __restrict__ Wg,
                                                  const float* __restrict__ bias,
                                                  float* __restrict__ out) {
    const int warp  = threadIdx.x >> 5;  // 0..7
    const int lane  = threadIdx.x & 31;
    const int gbase = blockIdx.x * 4;

    for (int t = warp; t < 4 * DO; t += 8) {
        const int g = gbase + (t >> 7);
        const int o = t & 127;

        const float inv_n = 1.0f / (float)max(g_noff[g + 1] - g_noff[g], 1);
        const float inv_e = 1.0f / (float)max(g_eoff[g + 1] - g_eoff[g], 1);

        float sn = 0.f, se = 0.f, sg = 0.f;

        const float* na = g_nagg + g * DN;
        const float* wn = Wn + o * DN;
        #pragma unroll
        for (int k = 0; k < DN / 32; k++) sn += na[lane + 32 * k] * wn[lane + 32 * k];

        const float* ea = g_eagg + g * DE;
        const float* we = We + o * DE;
        #pragma unroll
        for (int k = 0; k < DE / 32; k++) se += ea[lane + 32 * k] * we[lane + 32 * k];

        const float* ga = gf + g * DG;
        const float* wg = Wg + o * DG;
        #pragma unroll
        for (int k = 0; k < DG / 32; k++) sg += ga[lane + 32 * k] * wg[lane + 32 * k];

        float s = sn * inv_n + se * inv_e + sg;
        #pragma unroll
        for (int d = 16; d; d >>= 1) s += __shfl_xor_sync(0xffffffffu, s, d);

        if (lane == 0) out[g * DO + o] = s + bias[o];
    }
}

// ---------------------------------------------------------------------------
extern "C" void kernel_launch(void* const* d_in, const int* in_sizes, int n_in,
                              void* d_out, int out_size) {
    const float* node_features = (const float*)d_in[0];   // [N, 128]
    const float* edge_features = (const float*)d_in[1];   // [E, 64]
    const float* global_feats  = (const float*)d_in[2];   // [G, 128]
    const float* W_node        = (const float*)d_in[3];   // [128, 128]
    const float* W_edges       = (const float*)d_in[4];   // [128, 64]
    const float* W_global      = (const float*)d_in[5];   // [128, 128]
    const float* bias          = (const float*)d_in[6];   // [128]
    const int*   num_nodes     = (const int*)d_in[7];     // [G]
    const int*   num_edges     = (const int*)d_in[8];     // [G]
    float*       out           = (float*)d_out;           // [G, 128]

    scan_zero_kernel<<<64, 512>>>(num_nodes, num_edges);
    agg_kernel<<<2 * G * SLICES, 256>>>((const float4*)node_features,
                                        (const float4*)edge_features);
    out_kernel<<<(G + 3) / 4, 256>>>(global_feats, W_node, W_edges, W_global,
                                     bias, out);
}